// round 15
// baseline (speedup 1.0000x reference)
#include <cuda_runtime.h>
#include <math.h>

typedef unsigned long long u64;
typedef unsigned int u32;

__device__ __forceinline__ u64 pk2(float lo, float hi) {
    u64 r; asm("mov.b64 %0, {%1,%2};" : "=l"(r) : "f"(lo), "f"(hi)); return r;
}
__device__ __forceinline__ void upk2(u64 v, float& lo, float& hi) {
    asm("mov.b64 {%0,%1}, %2;" : "=f"(lo), "=f"(hi) : "l"(v));
}
__device__ __forceinline__ void ffma2_acc(u64& c, u64 a, u64 b) {
    asm("fma.rn.f32x2 %0, %1, %2, %0;" : "+l"(c) : "l"(a), "l"(b));
}
__device__ __forceinline__ float sqrt_ap(float x) {
    float r; asm("sqrt.approx.f32 %0, %1;" : "=f"(r) : "f"(x)); return r;
}
__device__ __forceinline__ u32 tf32_rna(float x) {
    u32 r; asm("cvt.rna.tf32.f32 %0, %1;" : "=r"(r) : "f"(x)); return r;
}
__device__ __forceinline__ void mma_tf32(float* d, u32 a0, u32 a1, u32 a2, u32 a3,
                                         u32 b0, u32 b1) {
    asm("mma.sync.aligned.m16n8k8.row.col.f32.tf32.tf32.f32 "
        "{%0,%1,%2,%3}, {%4,%5,%6,%7}, {%8,%9}, {%0,%1,%2,%3};"
        : "+f"(d[0]), "+f"(d[1]), "+f"(d[2]), "+f"(d[3])
        : "r"(a0), "r"(a1), "r"(a2), "r"(a3), "r"(b0), "r"(b1));
}

// ---------------- scratch (no allocations allowed -> __device__ globals) ---
__device__ float g_u1[32ull * 24 * 256 * 256];   // 201 MB
__device__ float g_s1[32ull * 27 * 256 * 256];   // 226 MB
__device__ float g_u2[32ull * 216 * 128 * 128];  // 453 MB

// ============== band-pass + modulus as implicit-GEMM (mma.sync tf32) =======
// D[px, n] = sum_k A[px, k] * B[k, n];  A = im2col(input, stride2, 7x7),
// K = 49 padded to 56, N: [r0..r7, i0..i7, phi] padded to 24.
// A split hi/lo (2 tf32 terms) -> only B-rounding error (~3e-4) survives.
// Warp-tile: M=16 px (x-strip) x N=24. CTA: 32x16 output px, 8 warps x 4 tiles.
#define OTX 32
#define OTY 16
#define TW  71            // input tile row stride (u32 words)
#define TH  38            // 2*OTY + 6 rows (ky pad row 7 included)
#define BN  24
#define BK  56

__global__ __launch_bounds__(256, 4) void band_mma_kernel(
    const float* __restrict__ in,     // [B*G, HIN, WIN]
    const float* __restrict__ phi,    // [3, 49]
    const float* __restrict__ psi_r,  // [24, 49]
    const float* __restrict__ psi_i,  // [24, 49]
    float* __restrict__ phi_out,      // [B, PHI_C, HOUT, WOUT]
    float* __restrict__ mod_out,      // [B, G*8, HOUT, WOUT]
    int HIN, int WIN, int HOUT, int WOUT,
    int G, int PHI_C)
{
    __shared__ u32 t_hi[TH * TW];
    __shared__ u32 t_lo[TH * TW];
    __shared__ u32 Bsm[BK * BN];

    const int tid = threadIdx.x;
    const int bz  = blockIdx.z;
    const int b   = bz / G;
    const int gch = bz - b * G;
    const int ce  = gch % 3;

    // --- B matrix [K=56][N=24], tf32: n 0..7 = psi_r, 8..15 = psi_i, 16 = phi
    for (int i = tid; i < BK * BN; i += 256) {
        int k = i / BN, n = i - k * BN;
        float w = 0.f;
        if (k < 49) {
            if (n < 8)        w = psi_r[(ce * 8 + n) * 49 + k];
            else if (n < 16)  w = psi_i[(ce * 8 + (n - 8)) * 49 + k];
            else if (n == 16) w = phi[ce * 49 + k];
        }
        Bsm[i] = tf32_rna(w);
    }

    // --- input tile load + hi/lo tf32 split
    const int ox0 = blockIdx.x * OTX;
    const int oy0 = blockIdx.y * OTY;
    const int ix0 = ox0 * 2 - 3;
    const int iy0 = oy0 * 2 - 3;
    const float* inp = in + (size_t)bz * HIN * WIN;

    for (int idx = tid; idx < TH * TW; idx += 256) {
        int r = idx / TW, c = idx - r * TW;
        int iy = iy0 + r, ix = ix0 + c;
        float v = 0.f;
        if ((unsigned)iy < (unsigned)HIN && (unsigned)ix < (unsigned)WIN)
            v = inp[(size_t)iy * WIN + ix];
        u32 hb = tf32_rna(v);
        float hv = __uint_as_float(hb);
        t_hi[idx] = hb;
        t_lo[idx] = tf32_rna(v - hv);
    }
    __syncthreads();

    const int wid  = tid >> 5;
    const int lane = tid & 31;
    const int qr   = lane >> 2;   // groupID 0..7 -> D rows qr, qr+8
    const int tig  = lane & 3;    // threadID in group

    // per-kstep A offsets: k -> (ky = k*147>>10, kx = k - 7*ky)
    int offA[7], offB[7];
    #pragma unroll
    for (int s = 0; s < 7; s++) {
        int ka = 8 * s + tig;
        int ky = (ka * 147) >> 10;
        offA[s] = ky * TW + (ka - ky * 7);
        int kb = ka + 4;
        int ky2 = (kb * 147) >> 10;
        offB[s] = ky2 * TW + (kb - ky2 * 7);
    }

    const int HW = HOUT * WOUT;
    float* mo_base = mod_out + ((size_t)(b * G + gch) * 8) * HW;
    float* po_base = phi_out + ((size_t)b * PHI_C + gch) * HW;
    const int bB = tig * BN + qr;         // B fragment base index

    #pragma unroll 1
    for (int mt = 0; mt < 4; mt++) {
        const int T   = wid + 8 * mt;     // 0..31 warp-tiles
        const int sx  = T & 1;
        const int oyl = T >> 1;
        const u32* sbh = t_hi + (2 * oyl) * TW + 32 * sx + 2 * qr;
        const u32* sbl = t_lo + (2 * oyl) * TW + 32 * sx + 2 * qr;

        float d0[4] = {0.f, 0.f, 0.f, 0.f};
        float d1[4] = {0.f, 0.f, 0.f, 0.f};
        float d2[4] = {0.f, 0.f, 0.f, 0.f};

        #pragma unroll
        for (int term = 0; term < 2; term++) {
            const u32* tp = term ? sbl : sbh;
            #pragma unroll
            for (int s = 0; s < 7; s++) {
                u32 a0 = tp[offA[s]],      a1 = tp[offA[s] + 16];
                u32 a2 = tp[offB[s]],      a3 = tp[offB[s] + 16];
                const u32* bp = Bsm + bB + 192 * s;   // (8s+tig)*24 + qr
                mma_tf32(d0, a0, a1, a2, a3, bp[0],  bp[96]);
                mma_tf32(d1, a0, a1, a2, a3, bp[8],  bp[104]);
                mma_tf32(d2, a0, a1, a2, a3, bp[16], bp[112]);
            }
        }

        // epilogue: thread holds cols {2tig, 2tig+1} of each n8 tile for
        // rows qr (d*[0], d*[1]) and qr+8 (d*[2], d*[3]).
        // n: d0 -> r_{2tig}, r_{2tig+1}; d1 -> i_{2tig}, i_{2tig+1}; d2[0] -> phi (tig==0)
        const int oy = oy0 + oyl;
        const int rb = oy * WOUT + ox0 + 16 * sx + qr;
        const int pe = 2 * tig, po = 2 * tig + 1;

        mo_base[(size_t)pe * HW + rb]     = sqrt_ap(d0[0] * d0[0] + d1[0] * d1[0]);
        mo_base[(size_t)po * HW + rb]     = sqrt_ap(d0[1] * d0[1] + d1[1] * d1[1]);
        mo_base[(size_t)pe * HW + rb + 8] = sqrt_ap(d0[2] * d0[2] + d1[2] * d1[2]);
        mo_base[(size_t)po * HW + rb + 8] = sqrt_ap(d0[3] * d0[3] + d1[3] * d1[3]);
        if (tig == 0) {
            po_base[rb]     = d2[0];
            po_base[rb + 8] = d2[2];
        }
        __syncthreads();   // tiles reused next mt? no — but keeps smem uniform; cheap
    }
}

// ============ depthwise stride-1 smoothing with phi[k%3], f32x2 ============
// (byte-identical to the R9/R13 best variant)
#define TSX 64
#define TSY 64
#define SW2 38
#define SH2 70

__global__ __launch_bounds__(256, 6) void smooth_kernel(
    const float* __restrict__ in,   // [B*CIN, H, W]
    const float* __restrict__ phi,  // [3, 49]
    float* __restrict__ out,        // [B, OUTC, H, W]
    int H, int W, int CIN, int OUTC, int OUTOFF)
{
    __shared__ __align__(16) u64 sp[SH2 * SW2];
    __shared__ __align__(16) u64 wdt[7 * 8];

    const int tid = threadIdx.x;
    const int bz  = blockIdx.z;
    const int b   = bz / CIN;
    const int k   = bz - b * CIN;
    const int ce  = k % 3;

    if (tid < 56) {
        int kx = tid >> 3, ky = tid & 7;
        float w = (ky < 7) ? phi[ce * 49 + ky * 7 + kx] : 0.f;
        wdt[tid] = pk2(w, w);
    }

    const int x0 = blockIdx.x * TSX;
    const int y0 = blockIdx.y * TSY;
    const float* inp = in + (size_t)bz * H * W;

    {
        int r = tid / SW2, c = tid - r * SW2;
        for (int idx = tid; idx < SH2 * SW2; idx += 256) {
            int iy  = y0 - 3 + r;
            int ixa = x0 - 3 + c;
            int ixb = ixa + 32;
            float va = 0.f, vb = 0.f;
            if ((unsigned)iy < (unsigned)H) {
                if ((unsigned)ixa < (unsigned)W) va = inp[(size_t)iy * W + ixa];
                if ((unsigned)ixb < (unsigned)W) vb = inp[(size_t)iy * W + ixb];
            }
            sp[idx] = pk2(va, vb);
            r += 6; c += 28; if (c >= SW2) { c -= SW2; r += 1; }
        }
    }
    __syncthreads();

    const int tx  = tid & 31;
    const int yc  = tid >> 5;
    const int ry0 = yc * 8;

    u64 acc[8];
    #pragma unroll
    for (int o = 0; o < 8; o++) acc[o] = 0ull;

    const u64* base = sp + ry0 * SW2 + tx;

    #pragma unroll 1
    for (int kx = 0; kx < 7; kx++) {
        const u64* col = base + kx;
        u64 w[7];
        {
            const ulonglong2* wv = (const ulonglong2*)(wdt + kx * 8);
            ulonglong2 q0 = wv[0], q1 = wv[1], q2 = wv[2];
            w[0] = q0.x; w[1] = q0.y; w[2] = q1.x; w[3] = q1.y;
            w[4] = q2.x; w[5] = q2.y;
            w[6] = *(const u64*)(wdt + kx * 8 + 6);
        }
        #pragma unroll
        for (int r = 0; r < 14; r++) {
            u64 v = col[r * SW2];
            #pragma unroll
            for (int ky = 0; ky < 7; ky++) {
                int o = r - ky;
                if (o >= 0 && o < 8)
                    ffma2_acc(acc[o], v, w[ky]);
            }
        }
    }

    float* po = out + ((size_t)b * OUTC + OUTOFF + k) * H * W
                    + (size_t)(y0 + ry0) * W + x0 + tx;
    #pragma unroll
    for (int o = 0; o < 8; o++) {
        float a, bv; upk2(acc[o], a, bv);
        po[(size_t)o * W]      = a;
        po[(size_t)o * W + 32] = bv;
    }
}

// ---------------- launcher -------------------------------------------------
extern "C" void kernel_launch(void* const* d_in, const int* in_sizes, int n_in,
                              void* d_out, int out_size)
{
    const float* x     = (const float*)d_in[0];
    const float* phi   = (const float*)d_in[1];
    const float* psi_r = (const float*)d_in[2];
    const float* psi_i = (const float*)d_in[3];
    float* out = (float*)d_out;

    float *u1, *s1, *u2;
    cudaGetSymbolAddress((void**)&u1, g_u1);
    cudaGetSymbolAddress((void**)&s1, g_s1);
    cudaGetSymbolAddress((void**)&u2, g_u2);

    // Stage 1: x [32,3,512,512] -> s0_phi into s1 ch 0-2, |U1| -> u1 [32,24,256,256]
    band_mma_kernel<<<dim3(256 / OTX, 256 / OTY, 32 * 3), 256>>>(
        x, phi, psi_r, psi_i, s1, u1, 512, 512, 256, 256, 3, 27);

    // u1_smooth -> s1 ch 3-26
    smooth_kernel<<<dim3(256 / TSX, 256 / TSY, 32 * 24), 256>>>(
        u1, phi, s1, 256, 256, 24, 27, 3);

    // Stage 2: s1 [32,27,256,256] -> s1_phi into out ch 0-26, |U2| -> u2 [32,216,128,128]
    band_mma_kernel<<<dim3(128 / OTX, 128 / OTY, 32 * 27), 256>>>(
        s1, phi, psi_r, psi_i, out, u2, 256, 256, 128, 128, 27, 243);

    // u2_smooth -> out ch 27-242
    smooth_kernel<<<dim3(128 / TSX, 128 / TSY, 32 * 216), 256>>>(
        u2, phi, out, 128, 128, 216, 243, 27);
}

// round 16
// speedup vs baseline: 1.2713x; 1.2713x over previous
#include <cuda_runtime.h>
#include <math.h>

typedef unsigned long long u64;
typedef unsigned int u32;

__device__ __forceinline__ u64 pk2(float lo, float hi) {
    u64 r; asm("mov.b64 %0, {%1,%2};" : "=l"(r) : "f"(lo), "f"(hi)); return r;
}
__device__ __forceinline__ void upk2(u64 v, float& lo, float& hi) {
    asm("mov.b64 {%0,%1}, %2;" : "=f"(lo), "=f"(hi) : "l"(v));
}
__device__ __forceinline__ void ffma2_acc(u64& c, u64 a, u64 b) {
    asm("fma.rn.f32x2 %0, %1, %2, %0;" : "+l"(c) : "l"(a), "l"(b));
}
__device__ __forceinline__ float sqrt_ap(float x) {
    float r; asm("sqrt.approx.f32 %0, %1;" : "=f"(r) : "f"(x)); return r;
}
__device__ __forceinline__ u32 tf32_rna(float x) {
    u32 r; asm("cvt.rna.tf32.f32 %0, %1;" : "=r"(r) : "f"(x)); return r;
}
__device__ __forceinline__ void mma_tf32(float* d, u32 a0, u32 a1, u32 a2, u32 a3,
                                         u32 b0, u32 b1) {
    asm("mma.sync.aligned.m16n8k8.row.col.f32.tf32.tf32.f32 "
        "{%0,%1,%2,%3}, {%4,%5,%6,%7}, {%8,%9}, {%0,%1,%2,%3};"
        : "+f"(d[0]), "+f"(d[1]), "+f"(d[2]), "+f"(d[3])
        : "r"(a0), "r"(a1), "r"(a2), "r"(a3), "r"(b0), "r"(b1));
}

// ---------------- scratch (no allocations allowed -> __device__ globals) ---
__device__ float g_u1[32ull * 24 * 256 * 256];   // 201 MB
__device__ float g_s1[32ull * 27 * 256 * 256];   // 226 MB
__device__ float g_u2[32ull * 216 * 128 * 128];  // 453 MB

// ============== band-pass + modulus as implicit-GEMM (mma.sync tf32) =======
// Single-term tf32 (A rounded once): rel_err budget ~2-4e-4 << 1e-3.
// D[px, n] = sum_k A[px, k] * B[k, n];  A = im2col(input, stride2, 7x7),
// K = 49 padded to 56, N: [r0..r7, i0..i7, phi] padded to 24.
// Warp-tile: M=16 px (x-strip) x N=24. CTA: 32x16 output px, 8 warps x 4 tiles.
#define OTX 32
#define OTY 16
#define TW  71            // input tile row stride (u32 words)
#define TH  38            // 2*OTY + 6 rows (ky pad row 7 included)
#define BN  24
#define BK  56

__global__ __launch_bounds__(256, 4) void band_mma_kernel(
    const float* __restrict__ in,     // [B*G, HIN, WIN]
    const float* __restrict__ phi,    // [3, 49]
    const float* __restrict__ psi_r,  // [24, 49]
    const float* __restrict__ psi_i,  // [24, 49]
    float* __restrict__ phi_out,      // [B, PHI_C, HOUT, WOUT]
    float* __restrict__ mod_out,      // [B, G*8, HOUT, WOUT]
    int HIN, int WIN, int HOUT, int WOUT,
    int G, int PHI_C)
{
    __shared__ u32 t_hi[TH * TW];
    __shared__ u32 Bsm[BK * BN];

    const int tid = threadIdx.x;
    const int bz  = blockIdx.z;
    const int b   = bz / G;
    const int gch = bz - b * G;
    const int ce  = gch % 3;

    // --- B matrix [K=56][N=24], tf32: n 0..7 = psi_r, 8..15 = psi_i, 16 = phi
    for (int i = tid; i < BK * BN; i += 256) {
        int k = i / BN, n = i - k * BN;
        float w = 0.f;
        if (k < 49) {
            if (n < 8)        w = psi_r[(ce * 8 + n) * 49 + k];
            else if (n < 16)  w = psi_i[(ce * 8 + (n - 8)) * 49 + k];
            else if (n == 16) w = phi[ce * 49 + k];
        }
        Bsm[i] = tf32_rna(w);
    }

    // --- input tile load, tf32-rounded once
    const int ox0 = blockIdx.x * OTX;
    const int oy0 = blockIdx.y * OTY;
    const int ix0 = ox0 * 2 - 3;
    const int iy0 = oy0 * 2 - 3;
    const float* inp = in + (size_t)bz * HIN * WIN;

    for (int idx = tid; idx < TH * TW; idx += 256) {
        int r = idx / TW, c = idx - r * TW;
        int iy = iy0 + r, ix = ix0 + c;
        float v = 0.f;
        if ((unsigned)iy < (unsigned)HIN && (unsigned)ix < (unsigned)WIN)
            v = inp[(size_t)iy * WIN + ix];
        t_hi[idx] = tf32_rna(v);
    }
    __syncthreads();

    const int wid  = tid >> 5;
    const int lane = tid & 31;
    const int qr   = lane >> 2;   // groupID 0..7 -> D rows qr, qr+8
    const int tig  = lane & 3;    // threadID in group

    // per-kstep A offsets: k -> (ky = k*147>>10, kx = k - 7*ky)
    int offA[7], offB[7];
    #pragma unroll
    for (int s = 0; s < 7; s++) {
        int ka = 8 * s + tig;
        int ky = (ka * 147) >> 10;
        offA[s] = ky * TW + (ka - ky * 7);
        int kb = ka + 4;
        int ky2 = (kb * 147) >> 10;
        offB[s] = ky2 * TW + (kb - ky2 * 7);
    }

    const int HW = HOUT * WOUT;
    float* mo_base = mod_out + ((size_t)(b * G + gch) * 8) * HW;
    float* po_base = phi_out + ((size_t)b * PHI_C + gch) * HW;
    const int bB = tig * BN + qr;         // B fragment base index

    #pragma unroll 1
    for (int mt = 0; mt < 4; mt++) {
        const int T   = wid + 8 * mt;     // 0..31 warp-tiles
        const int sx  = T & 1;
        const int oyl = T >> 1;
        const u32* tp = t_hi + (2 * oyl) * TW + 32 * sx + 2 * qr;

        float d0[4] = {0.f, 0.f, 0.f, 0.f};
        float d1[4] = {0.f, 0.f, 0.f, 0.f};
        float d2[4] = {0.f, 0.f, 0.f, 0.f};

        #pragma unroll
        for (int s = 0; s < 7; s++) {
            u32 a0 = tp[offA[s]],      a1 = tp[offA[s] + 16];
            u32 a2 = tp[offB[s]],      a3 = tp[offB[s] + 16];
            const u32* bp = Bsm + bB + 192 * s;   // (8s+tig)*24 + qr
            mma_tf32(d0, a0, a1, a2, a3, bp[0],  bp[96]);
            mma_tf32(d1, a0, a1, a2, a3, bp[8],  bp[104]);
            mma_tf32(d2, a0, a1, a2, a3, bp[16], bp[112]);
        }

        // epilogue: thread holds cols {2tig, 2tig+1} of each n8 tile for
        // rows qr (d*[0], d*[1]) and qr+8 (d*[2], d*[3]).
        const int oy = oy0 + oyl;
        const int rb = oy * WOUT + ox0 + 16 * sx + qr;
        const int pe = 2 * tig, po = 2 * tig + 1;

        mo_base[(size_t)pe * HW + rb]     = sqrt_ap(d0[0] * d0[0] + d1[0] * d1[0]);
        mo_base[(size_t)po * HW + rb]     = sqrt_ap(d0[1] * d0[1] + d1[1] * d1[1]);
        mo_base[(size_t)pe * HW + rb + 8] = sqrt_ap(d0[2] * d0[2] + d1[2] * d1[2]);
        mo_base[(size_t)po * HW + rb + 8] = sqrt_ap(d0[3] * d0[3] + d1[3] * d1[3]);
        if (tig == 0) {
            po_base[rb]     = d2[0];
            po_base[rb + 8] = d2[2];
        }
    }
}

// ============ depthwise stride-1 smoothing with phi[k%3], f32x2 ============
// (byte-identical to the R9/R13 best variant)
#define TSX 64
#define TSY 64
#define SW2 38
#define SH2 70

__global__ __launch_bounds__(256, 6) void smooth_kernel(
    const float* __restrict__ in,   // [B*CIN, H, W]
    const float* __restrict__ phi,  // [3, 49]
    float* __restrict__ out,        // [B, OUTC, H, W]
    int H, int W, int CIN, int OUTC, int OUTOFF)
{
    __shared__ __align__(16) u64 sp[SH2 * SW2];
    __shared__ __align__(16) u64 wdt[7 * 8];

    const int tid = threadIdx.x;
    const int bz  = blockIdx.z;
    const int b   = bz / CIN;
    const int k   = bz - b * CIN;
    const int ce  = k % 3;

    if (tid < 56) {
        int kx = tid >> 3, ky = tid & 7;
        float w = (ky < 7) ? phi[ce * 49 + ky * 7 + kx] : 0.f;
        wdt[tid] = pk2(w, w);
    }

    const int x0 = blockIdx.x * TSX;
    const int y0 = blockIdx.y * TSY;
    const float* inp = in + (size_t)bz * H * W;

    {
        int r = tid / SW2, c = tid - r * SW2;
        for (int idx = tid; idx < SH2 * SW2; idx += 256) {
            int iy  = y0 - 3 + r;
            int ixa = x0 - 3 + c;
            int ixb = ixa + 32;
            float va = 0.f, vb = 0.f;
            if ((unsigned)iy < (unsigned)H) {
                if ((unsigned)ixa < (unsigned)W) va = inp[(size_t)iy * W + ixa];
                if ((unsigned)ixb < (unsigned)W) vb = inp[(size_t)iy * W + ixb];
            }
            sp[idx] = pk2(va, vb);
            r += 6; c += 28; if (c >= SW2) { c -= SW2; r += 1; }
        }
    }
    __syncthreads();

    const int tx  = tid & 31;
    const int yc  = tid >> 5;
    const int ry0 = yc * 8;

    u64 acc[8];
    #pragma unroll
    for (int o = 0; o < 8; o++) acc[o] = 0ull;

    const u64* base = sp + ry0 * SW2 + tx;

    #pragma unroll 1
    for (int kx = 0; kx < 7; kx++) {
        const u64* col = base + kx;
        u64 w[7];
        {
            const ulonglong2* wv = (const ulonglong2*)(wdt + kx * 8);
            ulonglong2 q0 = wv[0], q1 = wv[1], q2 = wv[2];
            w[0] = q0.x; w[1] = q0.y; w[2] = q1.x; w[3] = q1.y;
            w[4] = q2.x; w[5] = q2.y;
            w[6] = *(const u64*)(wdt + kx * 8 + 6);
        }
        #pragma unroll
        for (int r = 0; r < 14; r++) {
            u64 v = col[r * SW2];
            #pragma unroll
            for (int ky = 0; ky < 7; ky++) {
                int o = r - ky;
                if (o >= 0 && o < 8)
                    ffma2_acc(acc[o], v, w[ky]);
            }
        }
    }

    float* po = out + ((size_t)b * OUTC + OUTOFF + k) * H * W
                    + (size_t)(y0 + ry0) * W + x0 + tx;
    #pragma unroll
    for (int o = 0; o < 8; o++) {
        float a, bv; upk2(acc[o], a, bv);
        po[(size_t)o * W]      = a;
        po[(size_t)o * W + 32] = bv;
    }
}

// ---------------- launcher -------------------------------------------------
extern "C" void kernel_launch(void* const* d_in, const int* in_sizes, int n_in,
                              void* d_out, int out_size)
{
    const float* x     = (const float*)d_in[0];
    const float* phi   = (const float*)d_in[1];
    const float* psi_r = (const float*)d_in[2];
    const float* psi_i = (const float*)d_in[3];
    float* out = (float*)d_out;

    float *u1, *s1, *u2;
    cudaGetSymbolAddress((void**)&u1, g_u1);
    cudaGetSymbolAddress((void**)&s1, g_s1);
    cudaGetSymbolAddress((void**)&u2, g_u2);

    // Stage 1: x [32,3,512,512] -> s0_phi into s1 ch 0-2, |U1| -> u1 [32,24,256,256]
    band_mma_kernel<<<dim3(256 / OTX, 256 / OTY, 32 * 3), 256>>>(
        x, phi, psi_r, psi_i, s1, u1, 512, 512, 256, 256, 3, 27);

    // u1_smooth -> s1 ch 3-26
    smooth_kernel<<<dim3(256 / TSX, 256 / TSY, 32 * 24), 256>>>(
        u1, phi, s1, 256, 256, 24, 27, 3);

    // Stage 2: s1 [32,27,256,256] -> s1_phi into out ch 0-26, |U2| -> u2 [32,216,128,128]
    band_mma_kernel<<<dim3(128 / OTX, 128 / OTY, 32 * 27), 256>>>(
        s1, phi, psi_r, psi_i, out, u2, 256, 256, 128, 128, 27, 243);

    // u2_smooth -> out ch 27-242
    smooth_kernel<<<dim3(128 / TSX, 128 / TSY, 32 * 216), 256>>>(
        u2, phi, out, 128, 128, 216, 243, 27);
}